// round 12
// baseline (speedup 1.0000x reference)
#include <cuda_runtime.h>
#include <cstdint>

#define N_NODES 200000
#define HID 32

// ---------------- scratch (static device globals; no allocation) ----------
__device__ int   g_deg[N_NODES];
__device__ float g_dinv[N_NODES];
__device__ float g_acc1[N_NODES];
__device__ float g_h2 [N_NODES * HID];   // h2 PRE-SCALED by dinv[n]
__device__ float g_acc2[N_NODES * HID];
__device__ float g_x2 [N_NODES * HID];

// ---------------- GCN stages ------------------------------------------------
__global__ void k_init(const float* __restrict__ ec, float* __restrict__ out_edge, int E) {
    int i = blockIdx.x * blockDim.x + threadIdx.x;
    if (i < N_NODES * HID / 4) ((float4*)g_acc2)[i] = make_float4(0.f, 0.f, 0.f, 0.f);
    if (i < N_NODES) { g_deg[i] = 0; g_acc1[i] = 0.f; }
    if (i < E) out_edge[i] = ec[i];
}
__global__ void k_deg(const int* __restrict__ dst, int E) {
    int e = blockIdx.x * blockDim.x + threadIdx.x;
    if (e < E) atomicAdd(&g_deg[dst[e]], 1);
}
__global__ void k_dinv() {
    int n = blockIdx.x * blockDim.x + threadIdx.x;
    if (n < N_NODES) g_dinv[n] = rsqrtf((float)(g_deg[n] + 1));
}
__global__ void k_acc1(const int* __restrict__ src, const int* __restrict__ dst, int E) {
    int e = blockIdx.x * blockDim.x + threadIdx.x;
    if (e < E) atomicAdd(&g_acc1[dst[e]], g_dinv[src[e]]);
}
__global__ void k_node1(const float* __restrict__ W1, const float* __restrict__ b1,
                        const float* __restrict__ W2) {
    __shared__ float sW1[HID], sB1[HID], sW2[HID * HID];
    for (int i = threadIdx.x; i < HID; i += blockDim.x) { sW1[i] = W1[i]; sB1[i] = b1[i]; }
    for (int i = threadIdx.x; i < HID * HID; i += blockDim.x) sW2[i] = W2[i];
    __syncthreads();
    int n = blockIdx.x * blockDim.x + threadIdx.x;
    if (n >= N_NODES) return;
    float dv = g_dinv[n];
    float s1 = dv * (g_acc1[n] + dv);
    float x1[HID];
#pragma unroll
    for (int k = 0; k < HID; k++) x1[k] = fmaxf(fmaf(sW1[k], s1, sB1[k]), 0.f);
    float h2[HID];
#pragma unroll
    for (int j = 0; j < HID; j++) h2[j] = 0.f;
#pragma unroll
    for (int i = 0; i < HID; i++) {
        float xi = x1[i];
#pragma unroll
        for (int j = 0; j < HID; j++) h2[j] = fmaf(xi, sW2[i * HID + j], h2[j]);
    }
    // store h2 pre-scaled by dinv[n]: message = h2s[src]*dinv[dst]; self = h2s*dv
    float4* o = (float4*)(g_h2 + (size_t)n * HID);
#pragma unroll
    for (int q = 0; q < 8; q++)
        o[q] = make_float4(h2[4 * q] * dv, h2[4 * q + 1] * dv,
                           h2[4 * q + 2] * dv, h2[4 * q + 3] * dv);
}
// vectorized message aggregation: 8 threads/edge, red.global.add.v4.f32
__global__ void k_msg(const int* __restrict__ src, const int* __restrict__ dst, int E) {
    int idx = blockIdx.x * blockDim.x + threadIdx.x;
    int e = idx >> 3, k = (idx & 7) << 2;
    if (e >= E) return;
    int s = src[e], d = dst[e];
    float nrm = g_dinv[d];                      // dinv[src] already folded into g_h2
    float4 v = *(const float4*)(g_h2 + (size_t)s * HID + k);
    float* p = g_acc2 + (size_t)d * HID + k;
    asm volatile("red.global.add.v4.f32 [%0], {%1,%2,%3,%4};"
                 :: "l"(p), "f"(v.x * nrm), "f"(v.y * nrm), "f"(v.z * nrm), "f"(v.w * nrm)
                 : "memory");
}
__global__ void k_node2(const float* __restrict__ b2) {
    int i = blockIdx.x * blockDim.x + threadIdx.x;
    if (i >= N_NODES * HID) return;
    int n = i >> 5, k = i & 31;
    float dv = g_dinv[n];
    g_x2[i] = fmaxf(g_acc2[i] + g_h2[i] * dv + b2[k], 0.f);   // g_h2 pre-scaled
}

// ---------------- stage 7: triangle MLP on tensor cores (LOCKED config) -----
#define WPB  4
#define TILE 16

#define SW1S 72
#define SW2S 40
#define SW3S 40
#define SAS  44
#define SHS  68
#define OFF_W1  0
#define OFF_W2  (40 * SW1S)                 // 2880
#define OFF_W3B (OFF_W2 + 64 * SW2S)        // 5440
#define OFF_B1  (OFF_W3B + 32 * SW3S)       // 6720
#define OFF_B2  (OFF_B1 + 64)               // 6784
#define OFF_B3  (OFF_B2 + 32)               // 6816
#define OFF_WARP 6824
#define WARP_FLOATS (TILE * SAS + TILE * SHS)       // 1792
#define SMEM_FLOATS (OFF_WARP + WPB * WARP_FLOATS)  // 13992
#define SMEM_BYTES  (SMEM_FLOATS * 4)               // 55968

__device__ __forceinline__ uint32_t f2tf(float x) {
    uint32_t r; asm("cvt.rna.tf32.f32 %0,%1;" : "=r"(r) : "f"(x)); return r;
}
__device__ __forceinline__ void mma_tf32(
    float& c0, float& c1, float& c2, float& c3,
    uint32_t a0, uint32_t a1, uint32_t a2, uint32_t a3,
    uint32_t b0, uint32_t b1)
{
    asm volatile(
        "mma.sync.aligned.m16n8k8.row.col.f32.tf32.tf32.f32 "
        "{%0,%1,%2,%3},{%4,%5,%6,%7},{%8,%9},{%0,%1,%2,%3};"
        : "+f"(c0), "+f"(c1), "+f"(c2), "+f"(c3)
        : "r"(a0), "r"(a1), "r"(a2), "r"(a3), "r"(b0), "r"(b1));
}

__global__ void __launch_bounds__(WPB * 32, 3) k_tri(
    const float* __restrict__ t12, const float* __restrict__ t13, const float* __restrict__ t23,
    const int* __restrict__ c12, const int* __restrict__ c13, const int* __restrict__ c23,
    const float* __restrict__ ec,
    const float* __restrict__ Wm1, const float* __restrict__ bm1,
    const float* __restrict__ Wm2, const float* __restrict__ bm2,
    const float* __restrict__ Wm3, const float* __restrict__ bm3,
    float* __restrict__ out_edge,
    float* __restrict__ o12, float* __restrict__ o13, float* __restrict__ o23, int T)
{
    extern __shared__ float smem[];
    uint32_t* sW1  = (uint32_t*)(smem + OFF_W1);
    uint32_t* sW2  = (uint32_t*)(smem + OFF_W2);
    uint32_t* sW3b = (uint32_t*)(smem + OFF_W3B);
    float* sB1 = smem + OFF_B1;
    float* sB2 = smem + OFF_B2;
    float* sB3 = smem + OFF_B3;

    const int tid = threadIdx.x;
    // ---- weights to shared (tf32 bits; 1/3 folded into W1 rows 3..34) ----
    for (int i = tid; i < 40 * SW1S; i += blockDim.x) {
        int row = i / SW1S, col = i % SW1S;
        float v = 0.f;
        if (row < 38 && col < 64) {
            v = Wm1[row * 64 + col];
            if (row >= 3 && row < 35) v *= (1.f / 3.f);
        }
        sW1[i] = f2tf(v);
    }
    for (int i = tid; i < 64 * SW2S; i += blockDim.x) {
        int row = i / SW2S, col = i % SW2S;
        sW2[i] = f2tf((col < 32) ? Wm2[row * 32 + col] : 0.f);
    }
    for (int i = tid; i < 32 * SW3S; i += blockDim.x) {
        int row = i / SW3S, col = i % SW3S;
        sW3b[i] = f2tf((col < 3) ? Wm3[row * 3 + col] : 0.f);
    }
    if (tid < 64) sB1[tid] = bm1[tid];
    if (tid < 32) sB2[tid] = bm2[tid];
    if (tid < 3)  sB3[tid] = bm3[tid];
    __syncthreads();

    const int wid  = tid >> 5;
    const int lane = tid & 31;
    const int grp  = lane >> 2;   // 0..7
    const int qd   = lane & 3;    // 0..3
    float* sA = smem + OFF_WARP + wid * WARP_FLOATS;   // [16][44]
    float* sH = sA + TILE * SAS;                       // [16][68]

    // ---- persistent register fragments (loop-invariant weights) ----
    uint32_t w2r[8][4][2];
#pragma unroll
    for (int kt = 0; kt < 8; kt++)
#pragma unroll
        for (int nt = 0; nt < 4; nt++) {
            w2r[kt][nt][0] = sW2[(kt * 8 + qd)     * SW2S + nt * 8 + grp];
            w2r[kt][nt][1] = sW2[(kt * 8 + qd + 4) * SW2S + nt * 8 + grp];
        }
    uint32_t w3r[4][2];
#pragma unroll
    for (int kt = 0; kt < 4; kt++) {
        w3r[kt][0] = sW3b[(kt * 8 + qd)     * SW3S + grp];
        w3r[kt][1] = sW3b[(kt * 8 + qd + 4) * SW3S + grp];
    }
    const float b3c0 = (2 * qd     < 3) ? sB3[2 * qd]     : 0.f;
    const float b3c1 = (2 * qd + 1 < 3) ? sB3[2 * qd + 1] : 0.f;

    const int ntiles = (T + TILE - 1) / TILE;
    const int gw = blockIdx.x * WPB + wid;
    const int gstride = gridDim.x * WPB;

    for (int tile = gw; tile < ntiles; tile += gstride) {
        const int t0 = tile * TILE;

        // ---- gather phase ------------------------------------------------
        int ia = 0, ib = 0, icx = 0;
        float f12 = 0.f, f13 = 0.f, f23 = 0.f;
        if (lane < TILE) {
            int t = t0 + lane;
            float ea = 0.f, eb = 0.f, ecv = 0.f;
            if (t < T) {
                ia = c12[t]; ib = c13[t]; icx = c23[t];
                f12 = t12[t]; f13 = t13[t]; f23 = t23[t];
                ea = __ldg(ec + ia); eb = __ldg(ec + ib); ecv = __ldg(ec + icx);
            }
            int* sIdx = (int*)sH;
            sIdx[lane] = ia; sIdx[16 + lane] = ib; sIdx[32 + lane] = icx;
            float* row = sA + lane * SAS;
            row[0] = f12; row[1] = f13; row[2] = f23;
            row[35] = ea; row[36] = eb; row[37] = ecv;
            row[38] = 0.f; row[39] = 0.f;
        }
        __syncwarp();
        {
            const int* sIdx = (const int*)sH;
#pragma unroll
            for (int half = 0; half < 2; half++) {
                const int base = half * 8;
                float va[8], vb[8], vc[8];
#pragma unroll
                for (int r = 0; r < 8; r++) va[r] = __ldg(g_x2 + (size_t)sIdx[base + r] * HID + lane);
#pragma unroll
                for (int r = 0; r < 8; r++) vb[r] = __ldg(g_x2 + (size_t)sIdx[16 + base + r] * HID + lane);
#pragma unroll
                for (int r = 0; r < 8; r++) vc[r] = __ldg(g_x2 + (size_t)sIdx[32 + base + r] * HID + lane);
#pragma unroll
                for (int r = 0; r < 8; r++)
                    sA[(base + r) * SAS + 3 + lane] = va[r] + vb[r] + vc[r];  // 1/3 in sW1
            }
        }
        __syncwarp();

        // ---- layer 1: [16x40] @ [40x64] (kt-outer, 8 independent accs) ---
        float a1[8][4];
#pragma unroll
        for (int nt = 0; nt < 8; nt++) {
            float2 bb = *(const float2*)(sB1 + nt * 8 + 2 * qd);
            a1[nt][0] = bb.x; a1[nt][1] = bb.y; a1[nt][2] = bb.x; a1[nt][3] = bb.y;
        }
#pragma unroll
        for (int kt = 0; kt < 5; kt++) {
            uint32_t A0 = f2tf(sA[grp * SAS + kt * 8 + qd]);
            uint32_t A1 = f2tf(sA[(grp + 8) * SAS + kt * 8 + qd]);
            uint32_t A2 = f2tf(sA[grp * SAS + kt * 8 + qd + 4]);
            uint32_t A3 = f2tf(sA[(grp + 8) * SAS + kt * 8 + qd + 4]);
#pragma unroll
            for (int nt = 0; nt < 8; nt++) {
                uint32_t b0 = sW1[(kt * 8 + qd)     * SW1S + nt * 8 + grp];
                uint32_t b1 = sW1[(kt * 8 + qd + 4) * SW1S + nt * 8 + grp];
                mma_tf32(a1[nt][0], a1[nt][1], a1[nt][2], a1[nt][3], A0, A1, A2, A3, b0, b1);
            }
        }
#pragma unroll
        for (int nt = 0; nt < 8; nt++) {
            int colc = nt * 8 + 2 * qd;
            sH[grp * SHS + colc]           = fmaxf(a1[nt][0], 0.f);
            sH[grp * SHS + colc + 1]       = fmaxf(a1[nt][1], 0.f);
            sH[(grp + 8) * SHS + colc]     = fmaxf(a1[nt][2], 0.f);
            sH[(grp + 8) * SHS + colc + 1] = fmaxf(a1[nt][3], 0.f);
        }
        __syncwarp();

        // ---- layer 2: [16x64] @ [64x32] (W2 in registers) ----------------
        float a2[4][4];
#pragma unroll
        for (int nt = 0; nt < 4; nt++) {
            float2 bb = *(const float2*)(sB2 + nt * 8 + 2 * qd);
            a2[nt][0] = bb.x; a2[nt][1] = bb.y; a2[nt][2] = bb.x; a2[nt][3] = bb.y;
        }
#pragma unroll
        for (int kt = 0; kt < 8; kt++) {
            uint32_t H0 = f2tf(sH[grp * SHS + kt * 8 + qd]);
            uint32_t H1 = f2tf(sH[(grp + 8) * SHS + kt * 8 + qd]);
            uint32_t H2 = f2tf(sH[grp * SHS + kt * 8 + qd + 4]);
            uint32_t H3 = f2tf(sH[(grp + 8) * SHS + kt * 8 + qd + 4]);
#pragma unroll
            for (int nt = 0; nt < 4; nt++)
                mma_tf32(a2[nt][0], a2[nt][1], a2[nt][2], a2[nt][3],
                         H0, H1, H2, H3, w2r[kt][nt][0], w2r[kt][nt][1]);
        }
#pragma unroll
        for (int nt = 0; nt < 4; nt++) {
            int colc = nt * 8 + 2 * qd;
            sA[grp * SAS + colc]           = fmaxf(a2[nt][0], 0.f);
            sA[grp * SAS + colc + 1]       = fmaxf(a2[nt][1], 0.f);
            sA[(grp + 8) * SAS + colc]     = fmaxf(a2[nt][2], 0.f);
            sA[(grp + 8) * SAS + colc + 1] = fmaxf(a2[nt][3], 0.f);
        }
        __syncwarp();

        // ---- layer 3: [16x32] @ [32x8(3)] via MMA (W3 in registers) ------
        float d0 = b3c0, d1 = b3c1, d2 = b3c0, d3 = b3c1;
#pragma unroll
        for (int kt = 0; kt < 4; kt++) {
            uint32_t A0 = f2tf(sA[grp * SAS + kt * 8 + qd]);
            uint32_t A1 = f2tf(sA[(grp + 8) * SAS + kt * 8 + qd]);
            uint32_t A2 = f2tf(sA[grp * SAS + kt * 8 + qd + 4]);
            uint32_t A3 = f2tf(sA[(grp + 8) * SAS + kt * 8 + qd + 4]);
            mma_tf32(d0, d1, d2, d3, A0, A1, A2, A3, w3r[kt][0], w3r[kt][1]);
        }
        float* sD = sH;   // reuse as [16][4]
        if (2 * qd < 3)     { sD[grp * 4 + 2 * qd]       = d0; sD[(grp + 8) * 4 + 2 * qd]     = d2; }
        if (2 * qd + 1 < 3) { sD[grp * 4 + 2 * qd + 1]   = d1; sD[(grp + 8) * 4 + 2 * qd + 1] = d3; }
        __syncwarp();

        // ---- epilogue ----------------------------------------------------
        if (lane < TILE && (t0 + lane) < T) {
            float4 dd = *(const float4*)(sD + lane * 4);
            int t = t0 + lane;
            o12[t] = f12 - dd.x;
            o13[t] = f13 - dd.y;
            o23[t] = f23 - dd.z;
            atomicAdd(out_edge + ia,  dd.x);
            atomicAdd(out_edge + ib,  dd.y);
            atomicAdd(out_edge + icx, dd.z);
        }
        __syncwarp();
    }
}

// ---------------- launcher ----------------------------------------------------
extern "C" void kernel_launch(void* const* d_in, const int* in_sizes, int n_in,
                              void* d_out, int out_size) {
    const float* edge_costs = (const float*)d_in[0];
    const float* t12 = (const float*)d_in[1];
    const float* t13 = (const float*)d_in[2];
    const float* t23 = (const float*)d_in[3];
    const int*   c12 = (const int*)d_in[4];
    const int*   c13 = (const int*)d_in[5];
    const int*   c23 = (const int*)d_in[6];
    const int*   eidx = (const int*)d_in[8];
    const float* W1  = (const float*)d_in[10];
    const float* b1  = (const float*)d_in[11];
    const float* W2  = (const float*)d_in[12];
    const float* b2  = (const float*)d_in[13];
    const float* Wm1 = (const float*)d_in[14];
    const float* bm1 = (const float*)d_in[15];
    const float* Wm2 = (const float*)d_in[16];
    const float* bm2 = (const float*)d_in[17];
    const float* Wm3 = (const float*)d_in[18];
    const float* bm3 = (const float*)d_in[19];

    int E = in_sizes[0];       // 200000
    int T = in_sizes[1];       // 2000000
    const int* src = eidx;
    const int* dst = eidx + E;

    float* out_edge = (float*)d_out;
    float* o12 = out_edge + E;
    float* o13 = o12 + T;
    float* o23 = o13 + T;

    const int B = 256;
    k_init <<<(N_NODES * HID + B - 1) / B, B>>>(edge_costs, out_edge, E);
    k_deg  <<<(E + B - 1) / B, B>>>(dst, E);
    k_dinv <<<(N_NODES + B - 1) / B, B>>>();
    k_acc1 <<<(E + B - 1) / B, B>>>(src, dst, E);
    k_node1<<<(N_NODES + B - 1) / B, B>>>(W1, b1, W2);
    k_msg  <<<((size_t)E * 8 + B - 1) / B, B>>>(src, dst, E);
    k_node2<<<(N_NODES * HID + B - 1) / B, B>>>(b2);

    cudaFuncSetAttribute(k_tri, cudaFuncAttributeMaxDynamicSharedMemorySize, SMEM_BYTES);
    k_tri<<<2368, WPB * 32, SMEM_BYTES>>>(t12, t13, t23, c12, c13, c23, edge_costs,
                                          Wm1, bm1, Wm2, bm2, Wm3, bm3,
                                          out_edge, o12, o13, o23, T);
}

// round 13
// speedup vs baseline: 1.2639x; 1.2639x over previous
#include <cuda_runtime.h>
#include <cuda_fp16.h>
#include <cstdint>

#define N_NODES 200000
#define HID 32

// ---------------- scratch (static device globals; no allocation) ----------
__device__ int   g_deg[N_NODES];
__device__ float g_dinv[N_NODES];
__device__ float g_acc1[N_NODES];
__device__ float g_h2 [N_NODES * HID];   // h2 PRE-SCALED by dinv[n]
__device__ float g_acc2[N_NODES * HID];
__device__ float g_x2 [N_NODES * HID];

// ---------------- GCN stages ------------------------------------------------
__global__ void k_init(const float* __restrict__ ec, float* __restrict__ out_edge, int E) {
    int i = blockIdx.x * blockDim.x + threadIdx.x;
    if (i < N_NODES * HID / 4) ((float4*)g_acc2)[i] = make_float4(0.f, 0.f, 0.f, 0.f);
    if (i < N_NODES) { g_deg[i] = 0; g_acc1[i] = 0.f; }
    if (i < E) out_edge[i] = ec[i];
}
__global__ void k_deg(const int* __restrict__ dst, int E) {
    int e = blockIdx.x * blockDim.x + threadIdx.x;
    if (e < E) atomicAdd(&g_deg[dst[e]], 1);
}
__global__ void k_dinv() {
    int n = blockIdx.x * blockDim.x + threadIdx.x;
    if (n < N_NODES) g_dinv[n] = rsqrtf((float)(g_deg[n] + 1));
}
__global__ void k_acc1(const int* __restrict__ src, const int* __restrict__ dst, int E) {
    int e = blockIdx.x * blockDim.x + threadIdx.x;
    if (e < E) atomicAdd(&g_acc1[dst[e]], g_dinv[src[e]]);
}
__global__ void k_node1(const float* __restrict__ W1, const float* __restrict__ b1,
                        const float* __restrict__ W2) {
    __shared__ float sW1[HID], sB1[HID], sW2[HID * HID];
    for (int i = threadIdx.x; i < HID; i += blockDim.x) { sW1[i] = W1[i]; sB1[i] = b1[i]; }
    for (int i = threadIdx.x; i < HID * HID; i += blockDim.x) sW2[i] = W2[i];
    __syncthreads();
    int n = blockIdx.x * blockDim.x + threadIdx.x;
    if (n >= N_NODES) return;
    float dv = g_dinv[n];
    float s1 = dv * (g_acc1[n] + dv);
    float x1[HID];
#pragma unroll
    for (int k = 0; k < HID; k++) x1[k] = fmaxf(fmaf(sW1[k], s1, sB1[k]), 0.f);
    float h2[HID];
#pragma unroll
    for (int j = 0; j < HID; j++) h2[j] = 0.f;
#pragma unroll
    for (int i = 0; i < HID; i++) {
        float xi = x1[i];
#pragma unroll
        for (int j = 0; j < HID; j++) h2[j] = fmaf(xi, sW2[i * HID + j], h2[j]);
    }
    float4* o = (float4*)(g_h2 + (size_t)n * HID);
#pragma unroll
    for (int q = 0; q < 8; q++)
        o[q] = make_float4(h2[4 * q] * dv, h2[4 * q + 1] * dv,
                           h2[4 * q + 2] * dv, h2[4 * q + 3] * dv);
}
__global__ void k_msg(const int* __restrict__ src, const int* __restrict__ dst, int E) {
    int idx = blockIdx.x * blockDim.x + threadIdx.x;
    int e = idx >> 3, k = (idx & 7) << 2;
    if (e >= E) return;
    int s = src[e], d = dst[e];
    float nrm = g_dinv[d];
    float4 v = *(const float4*)(g_h2 + (size_t)s * HID + k);
    float* p = g_acc2 + (size_t)d * HID + k;
    asm volatile("red.global.add.v4.f32 [%0], {%1,%2,%3,%4};"
                 :: "l"(p), "f"(v.x * nrm), "f"(v.y * nrm), "f"(v.z * nrm), "f"(v.w * nrm)
                 : "memory");
}
__global__ void k_node2(const float* __restrict__ b2) {
    int i = blockIdx.x * blockDim.x + threadIdx.x;
    if (i >= N_NODES * HID) return;
    int n = i >> 5, k = i & 31;
    float dv = g_dinv[n];
    g_x2[i] = fmaxf(g_acc2[i] + g_h2[i] * dv + b2[k], 0.f);
}

// ---------------- stage 7: triangle MLP, fp16 m16n8k16 tensor cores ---------
#define WPB  4
#define TILE 16
#define SAH  56     // sA row stride in halves (112B, conflict-free)
#define SHH  72     // sH row stride in halves (144B, conflict-free)
// byte offsets in dynamic smem
#define OFF_W1H  0                    // 3*8*32 uint2 = 6144 B
#define OFF_B1B  6144                 // 64 f32
#define OFF_B2B  6400                 // 32 f32
#define OFF_B3B  6528                 // 4 f32
#define OFF_STG  6560                 // 16B aligned
#define WARP_BYTES 4096               // sA 1792 + sH 2304
#define SMEM_BYTES 55968              // inflated: preserves 3-4 blocks/SM shape

__device__ __forceinline__ uint32_t packh2(float lo, float hi) {
    __half2 h = __floats2half2_rn(lo, hi);
    return *(uint32_t*)&h;
}
__device__ __forceinline__ void mma_f16(
    float& c0, float& c1, float& c2, float& c3,
    uint32_t a0, uint32_t a1, uint32_t a2, uint32_t a3,
    uint32_t b0, uint32_t b1)
{
    asm volatile(
        "mma.sync.aligned.m16n8k16.row.col.f32.f16.f16.f32 "
        "{%0,%1,%2,%3},{%4,%5,%6,%7},{%8,%9},{%0,%1,%2,%3};"
        : "+f"(c0), "+f"(c1), "+f"(c2), "+f"(c3)
        : "r"(a0), "r"(a1), "r"(a2), "r"(a3), "r"(b0), "r"(b1));
}

__global__ void __launch_bounds__(WPB * 32) k_tri(
    const float* __restrict__ t12, const float* __restrict__ t13, const float* __restrict__ t23,
    const int* __restrict__ c12, const int* __restrict__ c13, const int* __restrict__ c23,
    const float* __restrict__ ec,
    const float* __restrict__ Wm1, const float* __restrict__ bm1,
    const float* __restrict__ Wm2, const float* __restrict__ bm2,
    const float* __restrict__ Wm3, const float* __restrict__ bm3,
    float* __restrict__ out_edge,
    float* __restrict__ o12, float* __restrict__ o13, float* __restrict__ o23, int T)
{
    extern __shared__ char smem[];
    uint2* sW1h = (uint2*)(smem + OFF_W1H);   // [(kt*8+nt)*32 + qd*8+grp]
    float* sB1 = (float*)(smem + OFF_B1B);
    float* sB2 = (float*)(smem + OFF_B2B);
    float* sB3 = (float*)(smem + OFF_B3B);
    char*  stage = smem + OFF_STG;

    const int tid = threadIdx.x;

    // ---- W1 fragment table as half2 pairs (1/3 folded into rows 3..34) ----
    for (int i = tid; i < 3 * 8 * 32; i += blockDim.x) {
        int kt = i >> 8, nt = (i >> 5) & 7, j = i & 31;
        int q = j >> 3, g = j & 7;
        int col = nt * 8 + g;
        int r0 = kt * 16 + 2 * q;
        float v[4];
#pragma unroll
        for (int u = 0; u < 4; u++) {
            int r = r0 + (u >> 1) * 8 + (u & 1);
            float w = (r < 38) ? Wm1[r * 64 + col] : 0.f;
            if (r >= 3 && r < 35) w *= (1.f / 3.f);
            v[u] = w;
        }
        sW1h[i] = make_uint2(packh2(v[0], v[1]), packh2(v[2], v[3]));
    }
    // zero all staging (sA pad cols 38..47 stay zero forever)
    for (int i = tid; i < WPB * WARP_BYTES / 4; i += blockDim.x)
        ((uint32_t*)stage)[i] = 0;
    if (tid < 64) sB1[tid] = bm1[tid];
    if (tid < 32) sB2[tid] = bm2[tid];
    if (tid < 4)  sB3[tid] = (tid < 3) ? bm3[tid] : 0.f;
    __syncthreads();

    const int wid  = tid >> 5;
    const int lane = tid & 31;
    const int grp  = lane >> 2;   // 0..7
    const int qd   = lane & 3;    // 0..3
    const int fj   = (qd << 3) + grp;
    __half* sAh = (__half*)(stage + wid * WARP_BYTES);          // [16][56] halves
    __half* sHh = (__half*)(stage + wid * WARP_BYTES + 1792);   // [16][72] halves

    // ---- loop-invariant weight fragments in registers (from global) -------
    uint2 w2r[4][4];
#pragma unroll
    for (int kt = 0; kt < 4; kt++)
#pragma unroll
        for (int nt = 0; nt < 4; nt++) {
            int r0 = kt * 16 + 2 * qd, c = nt * 8 + grp;
            w2r[kt][nt] = make_uint2(
                packh2(Wm2[r0 * 32 + c],       Wm2[(r0 + 1) * 32 + c]),
                packh2(Wm2[(r0 + 8) * 32 + c], Wm2[(r0 + 9) * 32 + c]));
        }
    uint2 w3r[2];
#pragma unroll
    for (int kt = 0; kt < 2; kt++) {
        int r0 = kt * 16 + 2 * qd;
        float v0 = (grp < 3) ? Wm3[r0 * 3 + grp]       : 0.f;
        float v1 = (grp < 3) ? Wm3[(r0 + 1) * 3 + grp] : 0.f;
        float v2 = (grp < 3) ? Wm3[(r0 + 8) * 3 + grp] : 0.f;
        float v3 = (grp < 3) ? Wm3[(r0 + 9) * 3 + grp] : 0.f;
        w3r[kt] = make_uint2(packh2(v0, v1), packh2(v2, v3));
    }
    const float b3c0 = (2 * qd     < 3) ? sB3[2 * qd]     : 0.f;
    const float b3c1 = (2 * qd + 1 < 3) ? sB3[2 * qd + 1] : 0.f;

    const int ntiles = (T + TILE - 1) / TILE;
    const int gw = blockIdx.x * WPB + wid;
    const int gstride = gridDim.x * WPB;

    for (int tile = gw; tile < ntiles; tile += gstride) {
        const int t0 = tile * TILE;

        // ---- gather phase (smem index broadcast, no shuffles) --------------
        int ia = 0, ib = 0, icx = 0;
        float f12 = 0.f, f13 = 0.f, f23 = 0.f;
        if (lane < TILE) {
            int t = t0 + lane;
            float ea = 0.f, eb = 0.f, ecv = 0.f;
            if (t < T) {
                ia = c12[t]; ib = c13[t]; icx = c23[t];
                f12 = t12[t]; f13 = t13[t]; f23 = t23[t];
                ea = __ldg(ec + ia); eb = __ldg(ec + ib); ecv = __ldg(ec + icx);
            }
            int* sIdx = (int*)sHh;
            sIdx[lane] = ia; sIdx[16 + lane] = ib; sIdx[32 + lane] = icx;
            __half* row = sAh + lane * SAH;
            row[0]  = __float2half(f12);
            row[1]  = __float2half(f13);
            row[2]  = __float2half(f23);
            row[35] = __float2half(ea);
            row[36] = __float2half(eb);
            row[37] = __float2half(ecv);
        }
        __syncwarp();
        {
            const int* sIdx = (const int*)sHh;
#pragma unroll
            for (int half_ = 0; half_ < 2; half_++) {
                const int base = half_ * 8;
                float va[8], vb[8], vc[8];
#pragma unroll
                for (int r = 0; r < 8; r++) va[r] = __ldg(g_x2 + (size_t)sIdx[base + r] * HID + lane);
#pragma unroll
                for (int r = 0; r < 8; r++) vb[r] = __ldg(g_x2 + (size_t)sIdx[16 + base + r] * HID + lane);
#pragma unroll
                for (int r = 0; r < 8; r++) vc[r] = __ldg(g_x2 + (size_t)sIdx[32 + base + r] * HID + lane);
#pragma unroll
                for (int r = 0; r < 8; r++)
                    sAh[(base + r) * SAH + 3 + lane] = __float2half(va[r] + vb[r] + vc[r]);
            }
        }
        __syncwarp();

        // ---- layer 1: [16x48(40)] @ [48x64] fp16 ---------------------------
        float a1[8][4];
#pragma unroll
        for (int nt = 0; nt < 8; nt++) {
            float2 bb = *(const float2*)(sB1 + nt * 8 + 2 * qd);
            a1[nt][0] = bb.x; a1[nt][1] = bb.y; a1[nt][2] = bb.x; a1[nt][3] = bb.y;
        }
#pragma unroll
        for (int kt = 0; kt < 3; kt++) {
            uint32_t A0 = *(const uint32_t*)(sAh + grp * SAH + kt * 16 + 2 * qd);
            uint32_t A1 = *(const uint32_t*)(sAh + (grp + 8) * SAH + kt * 16 + 2 * qd);
            uint32_t A2 = *(const uint32_t*)(sAh + grp * SAH + kt * 16 + 2 * qd + 8);
            uint32_t A3 = *(const uint32_t*)(sAh + (grp + 8) * SAH + kt * 16 + 2 * qd + 8);
#pragma unroll
            for (int nt = 0; nt < 8; nt++) {
                uint2 b = sW1h[(kt * 8 + nt) * 32 + fj];
                mma_f16(a1[nt][0], a1[nt][1], a1[nt][2], a1[nt][3], A0, A1, A2, A3, b.x, b.y);
            }
        }
        __syncwarp();   // sIdx region (sHh) reused for h1 below
#pragma unroll
        for (int nt = 0; nt < 8; nt++) {
            int colc = nt * 8 + 2 * qd;
            *(uint32_t*)(sHh + grp * SHH + colc) =
                packh2(fmaxf(a1[nt][0], 0.f), fmaxf(a1[nt][1], 0.f));
            *(uint32_t*)(sHh + (grp + 8) * SHH + colc) =
                packh2(fmaxf(a1[nt][2], 0.f), fmaxf(a1[nt][3], 0.f));
        }
        __syncwarp();

        // ---- layer 2: [16x64] @ [64x32] fp16 (W2 in registers) -------------
        float a2[4][4];
#pragma unroll
        for (int nt = 0; nt < 4; nt++) {
            float2 bb = *(const float2*)(sB2 + nt * 8 + 2 * qd);
            a2[nt][0] = bb.x; a2[nt][1] = bb.y; a2[nt][2] = bb.x; a2[nt][3] = bb.y;
        }
#pragma unroll
        for (int kt = 0; kt < 4; kt++) {
            uint32_t H0 = *(const uint32_t*)(sHh + grp * SHH + kt * 16 + 2 * qd);
            uint32_t H1 = *(const uint32_t*)(sHh + (grp + 8) * SHH + kt * 16 + 2 * qd);
            uint32_t H2 = *(const uint32_t*)(sHh + grp * SHH + kt * 16 + 2 * qd + 8);
            uint32_t H3 = *(const uint32_t*)(sHh + (grp + 8) * SHH + kt * 16 + 2 * qd + 8);
#pragma unroll
            for (int nt = 0; nt < 4; nt++)
                mma_f16(a2[nt][0], a2[nt][1], a2[nt][2], a2[nt][3],
                        H0, H1, H2, H3, w2r[kt][nt].x, w2r[kt][nt].y);
        }
#pragma unroll
        for (int nt = 0; nt < 4; nt++) {
            int colc = nt * 8 + 2 * qd;
            *(uint32_t*)(sAh + grp * SAH + colc) =
                packh2(fmaxf(a2[nt][0], 0.f), fmaxf(a2[nt][1], 0.f));
            *(uint32_t*)(sAh + (grp + 8) * SAH + colc) =
                packh2(fmaxf(a2[nt][2], 0.f), fmaxf(a2[nt][3], 0.f));
        }
        __syncwarp();

        // ---- layer 3: [16x32] @ [32x8(3)] fp16 (W3 in registers) -----------
        float d0 = b3c0, d1 = b3c1, d2 = b3c0, d3 = b3c1;
#pragma unroll
        for (int kt = 0; kt < 2; kt++) {
            uint32_t A0 = *(const uint32_t*)(sAh + grp * SAH + kt * 16 + 2 * qd);
            uint32_t A1 = *(const uint32_t*)(sAh + (grp + 8) * SAH + kt * 16 + 2 * qd);
            uint32_t A2 = *(const uint32_t*)(sAh + grp * SAH + kt * 16 + 2 * qd + 8);
            uint32_t A3 = *(const uint32_t*)(sAh + (grp + 8) * SAH + kt * 16 + 2 * qd + 8);
            mma_f16(d0, d1, d2, d3, A0, A1, A2, A3, w3r[kt].x, w3r[kt].y);
        }
        float* sD = (float*)sHh;   // reuse as [16][4] f32
        if (2 * qd < 3)     { sD[grp * 4 + 2 * qd]     = d0; sD[(grp + 8) * 4 + 2 * qd]     = d2; }
        if (2 * qd + 1 < 3) { sD[grp * 4 + 2 * qd + 1] = d1; sD[(grp + 8) * 4 + 2 * qd + 1] = d3; }
        __syncwarp();

        // ---- epilogue -------------------------------------------------------
        if (lane < TILE && (t0 + lane) < T) {
            float4 dd = *(const float4*)(sD + lane * 4);
            int t = t0 + lane;
            o12[t] = f12 - dd.x;
            o13[t] = f13 - dd.y;
            o23[t] = f23 - dd.z;
            atomicAdd(out_edge + ia,  dd.x);
            atomicAdd(out_edge + ib,  dd.y);
            atomicAdd(out_edge + icx, dd.z);
        }
        __syncwarp();
    }
}

// ---------------- launcher ----------------------------------------------------
extern "C" void kernel_launch(void* const* d_in, const int* in_sizes, int n_in,
                              void* d_out, int out_size) {
    const float* edge_costs = (const float*)d_in[0];
    const float* t12 = (const float*)d_in[1];
    const float* t13 = (const float*)d_in[2];
    const float* t23 = (const float*)d_in[3];
    const int*   c12 = (const int*)d_in[4];
    const int*   c13 = (const int*)d_in[5];
    const int*   c23 = (const int*)d_in[6];
    const int*   eidx = (const int*)d_in[8];
    const float* W1  = (const float*)d_in[10];
    const float* b1  = (const float*)d_in[11];
    const float* W2  = (const float*)d_in[12];
    const float* b2  = (const float*)d_in[13];
    const float* Wm1 = (const float*)d_in[14];
    const float* bm1 = (const float*)d_in[15];
    const float* Wm2 = (const float*)d_in[16];
    const float* bm2 = (const float*)d_in[17];
    const float* Wm3 = (const float*)d_in[18];
    const float* bm3 = (const float*)d_in[19];

    int E = in_sizes[0];       // 200000
    int T = in_sizes[1];       // 2000000
    const int* src = eidx;
    const int* dst = eidx + E;

    float* out_edge = (float*)d_out;
    float* o12 = out_edge + E;
    float* o13 = o12 + T;
    float* o23 = o13 + T;

    const int B = 256;
    k_init <<<(N_NODES * HID + B - 1) / B, B>>>(edge_costs, out_edge, E);
    k_deg  <<<(E + B - 1) / B, B>>>(dst, E);
    k_dinv <<<(N_NODES + B - 1) / B, B>>>();
    k_acc1 <<<(E + B - 1) / B, B>>>(src, dst, E);
    k_node1<<<(N_NODES + B - 1) / B, B>>>(W1, b1, W2);
    k_msg  <<<((size_t)E * 8 + B - 1) / B, B>>>(src, dst, E);
    k_node2<<<(N_NODES * HID + B - 1) / B, B>>>(b2);

    cudaFuncSetAttribute(k_tri, cudaFuncAttributeMaxDynamicSharedMemorySize, SMEM_BYTES);
    k_tri<<<2368, WPB * 32, SMEM_BYTES>>>(t12, t13, t23, c12, c13, c23, edge_costs,
                                          Wm1, bm1, Wm2, bm2, Wm3, bm3,
                                          out_edge, o12, o13, o23, T);
}

// round 14
// speedup vs baseline: 1.2724x; 1.0068x over previous
#include <cuda_runtime.h>
#include <cuda_fp16.h>
#include <cstdint>

#define N_NODES 200000
#define HID 32

// ---------------- scratch (static device globals; no allocation) ----------
__device__ int   g_deg[N_NODES];
__device__ float g_dinv[N_NODES];
__device__ float g_acc1[N_NODES];
__device__ float g_h2 [N_NODES * HID];   // h2 PRE-SCALED by dinv[n]
__device__ float g_acc2[N_NODES * HID];
__device__ float g_x2 [N_NODES * HID];

// ---------------- GCN stages ------------------------------------------------
__global__ void k_init(const float* __restrict__ ec, float* __restrict__ out_edge, int E) {
    int i = blockIdx.x * blockDim.x + threadIdx.x;
    if (i < N_NODES * HID / 4) ((float4*)g_acc2)[i] = make_float4(0.f, 0.f, 0.f, 0.f);
    if (i < N_NODES) { g_deg[i] = 0; g_acc1[i] = 0.f; }
    if (i < E) out_edge[i] = ec[i];
}
__global__ void k_deg(const int* __restrict__ dst, int E) {
    int e = blockIdx.x * blockDim.x + threadIdx.x;
    if (e < E) atomicAdd(&g_deg[dst[e]], 1);
}
__global__ void k_dinv() {
    int n = blockIdx.x * blockDim.x + threadIdx.x;
    if (n < N_NODES) g_dinv[n] = rsqrtf((float)(g_deg[n] + 1));
}
__global__ void k_acc1(const int* __restrict__ src, const int* __restrict__ dst, int E) {
    int e = blockIdx.x * blockDim.x + threadIdx.x;
    if (e < E) atomicAdd(&g_acc1[dst[e]], g_dinv[src[e]]);
}
__global__ void k_node1(const float* __restrict__ W1, const float* __restrict__ b1,
                        const float* __restrict__ W2) {
    __shared__ float sW1[HID], sB1[HID], sW2[HID * HID];
    for (int i = threadIdx.x; i < HID; i += blockDim.x) { sW1[i] = W1[i]; sB1[i] = b1[i]; }
    for (int i = threadIdx.x; i < HID * HID; i += blockDim.x) sW2[i] = W2[i];
    __syncthreads();
    int n = blockIdx.x * blockDim.x + threadIdx.x;
    if (n >= N_NODES) return;
    float dv = g_dinv[n];
    float s1 = dv * (g_acc1[n] + dv);
    float x1[HID];
#pragma unroll
    for (int k = 0; k < HID; k++) x1[k] = fmaxf(fmaf(sW1[k], s1, sB1[k]), 0.f);
    float h2[HID];
#pragma unroll
    for (int j = 0; j < HID; j++) h2[j] = 0.f;
#pragma unroll
    for (int i = 0; i < HID; i++) {
        float xi = x1[i];
#pragma unroll
        for (int j = 0; j < HID; j++) h2[j] = fmaf(xi, sW2[i * HID + j], h2[j]);
    }
    float4* o = (float4*)(g_h2 + (size_t)n * HID);
#pragma unroll
    for (int q = 0; q < 8; q++)
        o[q] = make_float4(h2[4 * q] * dv, h2[4 * q + 1] * dv,
                           h2[4 * q + 2] * dv, h2[4 * q + 3] * dv);
}
__global__ void k_msg(const int* __restrict__ src, const int* __restrict__ dst, int E) {
    int idx = blockIdx.x * blockDim.x + threadIdx.x;
    int e = idx >> 3, k = (idx & 7) << 2;
    if (e >= E) return;
    int s = src[e], d = dst[e];
    float nrm = g_dinv[d];
    float4 v = *(const float4*)(g_h2 + (size_t)s * HID + k);
    float* p = g_acc2 + (size_t)d * HID + k;
    asm volatile("red.global.add.v4.f32 [%0], {%1,%2,%3,%4};"
                 :: "l"(p), "f"(v.x * nrm), "f"(v.y * nrm), "f"(v.z * nrm), "f"(v.w * nrm)
                 : "memory");
}
__global__ void k_node2(const float* __restrict__ b2) {
    int i = blockIdx.x * blockDim.x + threadIdx.x;
    if (i >= N_NODES * HID) return;
    int n = i >> 5, k = i & 31;
    float dv = g_dinv[n];
    g_x2[i] = fmaxf(g_acc2[i] + g_h2[i] * dv + b2[k], 0.f);
}

// ---------------- stage 7: triangle MLP, fp16 m16n8k16 tensor cores ---------
#define WPB  4
#define TILE 16
#define SAH  56     // sA row stride in halves (112B, conflict-free)
#define SHH  72     // sH row stride in halves (144B, conflict-free)
// byte offsets in dynamic smem
#define OFF_W1H  0                    // 3*8*32 uint2 = 6144 B
#define OFF_B1B  6144                 // 64 f32
#define OFF_B2B  6400                 // 32 f32
#define OFF_B3B  6528                 // 4 f32
#define OFF_STG  6560                 // 16B aligned
#define WARP_BYTES 4096               // sA 1792 + sH 2304
#define SMEM_BYTES (OFF_STG + WPB * WARP_BYTES)   // 22944: allows 5+ blocks/SM

__device__ __forceinline__ uint32_t packh2(float lo, float hi) {
    __half2 h = __floats2half2_rn(lo, hi);
    return *(uint32_t*)&h;
}
__device__ __forceinline__ void mma_f16(
    float& c0, float& c1, float& c2, float& c3,
    uint32_t a0, uint32_t a1, uint32_t a2, uint32_t a3,
    uint32_t b0, uint32_t b1)
{
    asm volatile(
        "mma.sync.aligned.m16n8k16.row.col.f32.f16.f16.f32 "
        "{%0,%1,%2,%3},{%4,%5,%6,%7},{%8,%9},{%0,%1,%2,%3};"
        : "+f"(c0), "+f"(c1), "+f"(c2), "+f"(c3)
        : "r"(a0), "r"(a1), "r"(a2), "r"(a3), "r"(b0), "r"(b1));
}

__global__ void __launch_bounds__(WPB * 32, 5) k_tri(
    const float* __restrict__ t12, const float* __restrict__ t13, const float* __restrict__ t23,
    const int* __restrict__ c12, const int* __restrict__ c13, const int* __restrict__ c23,
    const float* __restrict__ ec,
    const float* __restrict__ Wm1, const float* __restrict__ bm1,
    const float* __restrict__ Wm2, const float* __restrict__ bm2,
    const float* __restrict__ Wm3, const float* __restrict__ bm3,
    float* __restrict__ out_edge,
    float* __restrict__ o12, float* __restrict__ o13, float* __restrict__ o23, int T)
{
    extern __shared__ char smem[];
    uint2* sW1h = (uint2*)(smem + OFF_W1H);   // [(kt*8+nt)*32 + qd*8+grp]
    float* sB1 = (float*)(smem + OFF_B1B);
    float* sB2 = (float*)(smem + OFF_B2B);
    float* sB3 = (float*)(smem + OFF_B3B);
    char*  stage = smem + OFF_STG;

    const int tid = threadIdx.x;

    // ---- W1 fragment table as half2 pairs (1/3 folded into rows 3..34) ----
    for (int i = tid; i < 3 * 8 * 32; i += blockDim.x) {
        int kt = i >> 8, nt = (i >> 5) & 7, j = i & 31;
        int q = j >> 3, g = j & 7;
        int col = nt * 8 + g;
        int r0 = kt * 16 + 2 * q;
        float v[4];
#pragma unroll
        for (int u = 0; u < 4; u++) {
            int r = r0 + (u >> 1) * 8 + (u & 1);
            float w = (r < 38) ? Wm1[r * 64 + col] : 0.f;
            if (r >= 3 && r < 35) w *= (1.f / 3.f);
            v[u] = w;
        }
        sW1h[i] = make_uint2(packh2(v[0], v[1]), packh2(v[2], v[3]));
    }
    // zero all staging (sA pad cols 38..47 stay zero forever)
    for (int i = tid; i < WPB * WARP_BYTES / 4; i += blockDim.x)
        ((uint32_t*)stage)[i] = 0;
    if (tid < 64) sB1[tid] = bm1[tid];
    if (tid < 32) sB2[tid] = bm2[tid];
    if (tid < 4)  sB3[tid] = (tid < 3) ? bm3[tid] : 0.f;
    __syncthreads();

    const int wid  = tid >> 5;
    const int lane = tid & 31;
    const int grp  = lane >> 2;   // 0..7
    const int qd   = lane & 3;    // 0..3
    const int fj   = (qd << 3) + grp;
    __half* sAh = (__half*)(stage + wid * WARP_BYTES);          // [16][56] halves
    __half* sHh = (__half*)(stage + wid * WARP_BYTES + 1792);   // [16][72] halves

    // ---- loop-invariant weight fragments in registers (from global) -------
    uint2 w2r[4][4];
#pragma unroll
    for (int kt = 0; kt < 4; kt++)
#pragma unroll
        for (int nt = 0; nt < 4; nt++) {
            int r0 = kt * 16 + 2 * qd, c = nt * 8 + grp;
            w2r[kt][nt] = make_uint2(
                packh2(Wm2[r0 * 32 + c],       Wm2[(r0 + 1) * 32 + c]),
                packh2(Wm2[(r0 + 8) * 32 + c], Wm2[(r0 + 9) * 32 + c]));
        }
    uint2 w3r[2];
#pragma unroll
    for (int kt = 0; kt < 2; kt++) {
        int r0 = kt * 16 + 2 * qd;
        float v0 = (grp < 3) ? Wm3[r0 * 3 + grp]       : 0.f;
        float v1 = (grp < 3) ? Wm3[(r0 + 1) * 3 + grp] : 0.f;
        float v2 = (grp < 3) ? Wm3[(r0 + 8) * 3 + grp] : 0.f;
        float v3 = (grp < 3) ? Wm3[(r0 + 9) * 3 + grp] : 0.f;
        w3r[kt] = make_uint2(packh2(v0, v1), packh2(v2, v3));
    }
    const float b3c0 = (2 * qd     < 3) ? sB3[2 * qd]     : 0.f;
    const float b3c1 = (2 * qd + 1 < 3) ? sB3[2 * qd + 1] : 0.f;

    const int ntiles = (T + TILE - 1) / TILE;
    const int gw = blockIdx.x * WPB + wid;
    const int gstride = gridDim.x * WPB;

    for (int tile = gw; tile < ntiles; tile += gstride) {
        const int t0 = tile * TILE;

        // ---- gather phase (smem index broadcast, no shuffles) --------------
        int ia = 0, ib = 0, icx = 0;
        float f12 = 0.f, f13 = 0.f, f23 = 0.f;
        if (lane < TILE) {
            int t = t0 + lane;
            float ea = 0.f, eb = 0.f, ecv = 0.f;
            if (t < T) {
                ia = c12[t]; ib = c13[t]; icx = c23[t];
                f12 = t12[t]; f13 = t13[t]; f23 = t23[t];
                ea = __ldg(ec + ia); eb = __ldg(ec + ib); ecv = __ldg(ec + icx);
            }
            int* sIdx = (int*)sHh;
            sIdx[lane] = ia; sIdx[16 + lane] = ib; sIdx[32 + lane] = icx;
            __half* row = sAh + lane * SAH;
            row[0]  = __float2half(f12);
            row[1]  = __float2half(f13);
            row[2]  = __float2half(f23);
            row[35] = __float2half(ea);
            row[36] = __float2half(eb);
            row[37] = __float2half(ecv);
        }
        __syncwarp();
        {
            const int* sIdx = (const int*)sHh;
#pragma unroll
            for (int half_ = 0; half_ < 2; half_++) {
                const int base = half_ * 8;
                float va[8], vb[8], vc[8];
#pragma unroll
                for (int r = 0; r < 8; r++) va[r] = __ldg(g_x2 + (size_t)sIdx[base + r] * HID + lane);
#pragma unroll
                for (int r = 0; r < 8; r++) vb[r] = __ldg(g_x2 + (size_t)sIdx[16 + base + r] * HID + lane);
#pragma unroll
                for (int r = 0; r < 8; r++) vc[r] = __ldg(g_x2 + (size_t)sIdx[32 + base + r] * HID + lane);
#pragma unroll
                for (int r = 0; r < 8; r++)
                    sAh[(base + r) * SAH + 3 + lane] = __float2half(va[r] + vb[r] + vc[r]);
            }
        }
        __syncwarp();

        // ---- layer 1: [16x48(40)] @ [48x64] fp16 ---------------------------
        float a1[8][4];
#pragma unroll
        for (int nt = 0; nt < 8; nt++) {
            float2 bb = *(const float2*)(sB1 + nt * 8 + 2 * qd);
            a1[nt][0] = bb.x; a1[nt][1] = bb.y; a1[nt][2] = bb.x; a1[nt][3] = bb.y;
        }
#pragma unroll
        for (int kt = 0; kt < 3; kt++) {
            uint32_t A0 = *(const uint32_t*)(sAh + grp * SAH + kt * 16 + 2 * qd);
            uint32_t A1 = *(const uint32_t*)(sAh + (grp + 8) * SAH + kt * 16 + 2 * qd);
            uint32_t A2 = *(const uint32_t*)(sAh + grp * SAH + kt * 16 + 2 * qd + 8);
            uint32_t A3 = *(const uint32_t*)(sAh + (grp + 8) * SAH + kt * 16 + 2 * qd + 8);
#pragma unroll
            for (int nt = 0; nt < 8; nt++) {
                uint2 b = sW1h[(kt * 8 + nt) * 32 + fj];
                mma_f16(a1[nt][0], a1[nt][1], a1[nt][2], a1[nt][3], A0, A1, A2, A3, b.x, b.y);
            }
        }
        __syncwarp();   // sIdx region (sHh) reused for h1 below
#pragma unroll
        for (int nt = 0; nt < 8; nt++) {
            int colc = nt * 8 + 2 * qd;
            *(uint32_t*)(sHh + grp * SHH + colc) =
                packh2(fmaxf(a1[nt][0], 0.f), fmaxf(a1[nt][1], 0.f));
            *(uint32_t*)(sHh + (grp + 8) * SHH + colc) =
                packh2(fmaxf(a1[nt][2], 0.f), fmaxf(a1[nt][3], 0.f));
        }
        __syncwarp();

        // ---- layer 2: [16x64] @ [64x32] fp16 (W2 in registers) -------------
        float a2[4][4];
#pragma unroll
        for (int nt = 0; nt < 4; nt++) {
            float2 bb = *(const float2*)(sB2 + nt * 8 + 2 * qd);
            a2[nt][0] = bb.x; a2[nt][1] = bb.y; a2[nt][2] = bb.x; a2[nt][3] = bb.y;
        }
#pragma unroll
        for (int kt = 0; kt < 4; kt++) {
            uint32_t H0 = *(const uint32_t*)(sHh + grp * SHH + kt * 16 + 2 * qd);
            uint32_t H1 = *(const uint32_t*)(sHh + (grp + 8) * SHH + kt * 16 + 2 * qd);
            uint32_t H2 = *(const uint32_t*)(sHh + grp * SHH + kt * 16 + 2 * qd + 8);
            uint32_t H3 = *(const uint32_t*)(sHh + (grp + 8) * SHH + kt * 16 + 2 * qd + 8);
#pragma unroll
            for (int nt = 0; nt < 4; nt++)
                mma_f16(a2[nt][0], a2[nt][1], a2[nt][2], a2[nt][3],
                        H0, H1, H2, H3, w2r[kt][nt].x, w2r[kt][nt].y);
        }
#pragma unroll
        for (int nt = 0; nt < 4; nt++) {
            int colc = nt * 8 + 2 * qd;
            *(uint32_t*)(sAh + grp * SAH + colc) =
                packh2(fmaxf(a2[nt][0], 0.f), fmaxf(a2[nt][1], 0.f));
            *(uint32_t*)(sAh + (grp + 8) * SAH + colc) =
                packh2(fmaxf(a2[nt][2], 0.f), fmaxf(a2[nt][3], 0.f));
        }
        __syncwarp();

        // ---- layer 3: [16x32] @ [32x8(3)] fp16 (W3 in registers) -----------
        float d0 = b3c0, d1 = b3c1, d2 = b3c0, d3 = b3c1;
#pragma unroll
        for (int kt = 0; kt < 2; kt++) {
            uint32_t A0 = *(const uint32_t*)(sAh + grp * SAH + kt * 16 + 2 * qd);
            uint32_t A1 = *(const uint32_t*)(sAh + (grp + 8) * SAH + kt * 16 + 2 * qd);
            uint32_t A2 = *(const uint32_t*)(sAh + grp * SAH + kt * 16 + 2 * qd + 8);
            uint32_t A3 = *(const uint32_t*)(sAh + (grp + 8) * SAH + kt * 16 + 2 * qd + 8);
            mma_f16(d0, d1, d2, d3, A0, A1, A2, A3, w3r[kt].x, w3r[kt].y);
        }
        float* sD = (float*)sHh;   // reuse as [16][4] f32
        if (2 * qd < 3)     { sD[grp * 4 + 2 * qd]     = d0; sD[(grp + 8) * 4 + 2 * qd]     = d2; }
        if (2 * qd + 1 < 3) { sD[grp * 4 + 2 * qd + 1] = d1; sD[(grp + 8) * 4 + 2 * qd + 1] = d3; }
        __syncwarp();

        // ---- epilogue -------------------------------------------------------
        if (lane < TILE && (t0 + lane) < T) {
            float4 dd = *(const float4*)(sD + lane * 4);
            int t = t0 + lane;
            o12[t] = f12 - dd.x;
            o13[t] = f13 - dd.y;
            o23[t] = f23 - dd.z;
            atomicAdd(out_edge + ia,  dd.x);
            atomicAdd(out_edge + ib,  dd.y);
            atomicAdd(out_edge + icx, dd.z);
        }
        __syncwarp();
    }
}

// ---------------- launcher ----------------------------------------------------
extern "C" void kernel_launch(void* const* d_in, const int* in_sizes, int n_in,
                              void* d_out, int out_size) {
    const float* edge_costs = (const float*)d_in[0];
    const float* t12 = (const float*)d_in[1];
    const float* t13 = (const float*)d_in[2];
    const float* t23 = (const float*)d_in[3];
    const int*   c12 = (const int*)d_in[4];
    const int*   c13 = (const int*)d_in[5];
    const int*   c23 = (const int*)d_in[6];
    const int*   eidx = (const int*)d_in[8];
    const float* W1  = (const float*)d_in[10];
    const float* b1  = (const float*)d_in[11];
    const float* W2  = (const float*)d_in[12];
    const float* b2  = (const float*)d_in[13];
    const float* Wm1 = (const float*)d_in[14];
    const float* bm1 = (const float*)d_in[15];
    const float* Wm2 = (const float*)d_in[16];
    const float* bm2 = (const float*)d_in[17];
    const float* Wm3 = (const float*)d_in[18];
    const float* bm3 = (const float*)d_in[19];

    int E = in_sizes[0];       // 200000
    int T = in_sizes[1];       // 2000000
    const int* src = eidx;
    const int* dst = eidx + E;

    float* out_edge = (float*)d_out;
    float* o12 = out_edge + E;
    float* o13 = o12 + T;
    float* o23 = o13 + T;

    const int B = 256;
    k_init <<<(N_NODES * HID + B - 1) / B, B>>>(edge_costs, out_edge, E);
    k_deg  <<<(E + B - 1) / B, B>>>(dst, E);
    k_dinv <<<(N_NODES + B - 1) / B, B>>>();
    k_acc1 <<<(E + B - 1) / B, B>>>(src, dst, E);
    k_node1<<<(N_NODES + B - 1) / B, B>>>(W1, b1, W2);
    k_msg  <<<((size_t)E * 8 + B - 1) / B, B>>>(src, dst, E);
    k_node2<<<(N_NODES * HID + B - 1) / B, B>>>(b2);

    cudaFuncSetAttribute(k_tri, cudaFuncAttributeMaxDynamicSharedMemorySize, SMEM_BYTES);
    k_tri<<<2368, WPB * 32, SMEM_BYTES>>>(t12, t13, t23, c12, c13, c23, edge_costs,
                                          Wm1, bm1, Wm2, bm2, Wm3, bm3,
                                          out_edge, o12, o13, o23, T);
}